// round 13
// baseline (speedup 1.0000x reference)
#include <cuda_runtime.h>
#include <cuda_bf16.h>
#include <math_constants.h>
#include <cstdint>

// Problem constants
#define BATCH 8
#define SEQ   1024
#define DIM   1024
#define HEADS 16
#define HDIM  64
#define MTOT  (BATCH * SEQ)   // 8192

// ---------------------------------------------------------------------------
// Scratch (device globals — allocation-free rule)
// ---------------------------------------------------------------------------
__device__ __align__(16) float g_qkv[MTOT * 3 * DIM];   // [8192, 3072]
__device__ __align__(16) float g_att[MTOT * DIM];       // [8192, 1024]
__device__ __align__(16) __nv_bfloat16 g_xhi[MTOT * DIM];
__device__ __align__(16) __nv_bfloat16 g_xlo[MTOT * DIM];
__device__ __align__(16) __nv_bfloat16 g_ahi[MTOT * DIM];
__device__ __align__(16) __nv_bfloat16 g_alo[MTOT * DIM];
__device__ __align__(16) __nv_bfloat16 g_wqhiT[3 * DIM * DIM];  // [3072, 1024]
__device__ __align__(16) __nv_bfloat16 g_wqloT[3 * DIM * DIM];
__device__ __align__(16) __nv_bfloat16 g_wphiT[DIM * DIM];      // [1024, 1024]
__device__ __align__(16) __nv_bfloat16 g_wploT[DIM * DIM];

// ---------------------------------------------------------------------------
// Portable PTX helpers (NO 'a'-suffix features — harness compiles compute_103)
// ---------------------------------------------------------------------------
__device__ __forceinline__ uint32_t smem_u32(const void* p) {
    uint32_t a;
    asm("{ .reg .u64 t; cvta.to.shared.u64 t, %1; cvt.u32.u64 %0, t; }"
        : "=r"(a) : "l"(p));
    return a;
}

__device__ __forceinline__ void cp_async16(uint32_t saddr, const void* gaddr) {
    asm volatile("cp.async.cg.shared.global [%0], [%1], 16;"
                 :: "r"(saddr), "l"(gaddr));
}
#define CP_COMMIT()  asm volatile("cp.async.commit_group;" ::: "memory")
#define CP_WAIT(n)   asm volatile("cp.async.wait_group %0;" :: "n"(n) : "memory")

__device__ __forceinline__ void ldmatrix_x4(uint32_t& r0, uint32_t& r1,
                                            uint32_t& r2, uint32_t& r3,
                                            uint32_t addr) {
    asm volatile("ldmatrix.sync.aligned.m8n8.x4.shared.b16 {%0,%1,%2,%3}, [%4];"
                 : "=r"(r0), "=r"(r1), "=r"(r2), "=r"(r3) : "r"(addr));
}

__device__ __forceinline__ void mma16816(float* d, const uint32_t* a,
                                         uint32_t b0, uint32_t b1) {
    asm volatile(
        "mma.sync.aligned.m16n8k16.row.col.f32.bf16.bf16.f32 "
        "{%0,%1,%2,%3}, {%4,%5,%6,%7}, {%8,%9}, {%0,%1,%2,%3};"
        : "+f"(d[0]), "+f"(d[1]), "+f"(d[2]), "+f"(d[3])
        : "r"(a[0]), "r"(a[1]), "r"(a[2]), "r"(a[3]), "r"(b0), "r"(b1));
}

// ---------------------------------------------------------------------------
// fp32 -> bf16 hi/lo split (vectorized x4)
// ---------------------------------------------------------------------------
__global__ void cvt_split(const float* __restrict__ src,
                          __nv_bfloat16* __restrict__ hi,
                          __nv_bfloat16* __restrict__ lo, int n4)
{
    int i = blockIdx.x * blockDim.x + threadIdx.x;
    if (i >= n4) return;
    float4 v = ((const float4*)src)[i];
    __nv_bfloat16 h0 = __float2bfloat16_rn(v.x);
    __nv_bfloat16 h1 = __float2bfloat16_rn(v.y);
    __nv_bfloat16 h2 = __float2bfloat16_rn(v.z);
    __nv_bfloat16 h3 = __float2bfloat16_rn(v.w);
    __nv_bfloat16 l0 = __float2bfloat16_rn(v.x - __bfloat162float(h0));
    __nv_bfloat16 l1 = __float2bfloat16_rn(v.y - __bfloat162float(h1));
    __nv_bfloat16 l2 = __float2bfloat16_rn(v.z - __bfloat162float(h2));
    __nv_bfloat16 l3 = __float2bfloat16_rn(v.w - __bfloat162float(h3));
    __nv_bfloat162* hp = (__nv_bfloat162*)hi;
    __nv_bfloat162* lp = (__nv_bfloat162*)lo;
    hp[i * 2 + 0] = __nv_bfloat162(h0, h1);
    hp[i * 2 + 1] = __nv_bfloat162(h2, h3);
    lp[i * 2 + 0] = __nv_bfloat162(l0, l1);
    lp[i * 2 + 1] = __nv_bfloat162(l2, l3);
}

// ---------------------------------------------------------------------------
// Transpose W[K=1024, Ntot] -> hiT/loT [Ntot, 1024] (bf16 split)
// ---------------------------------------------------------------------------
__global__ void transpose_split(const float* __restrict__ W,
                                __nv_bfloat16* __restrict__ hiT,
                                __nv_bfloat16* __restrict__ loT, int Ntot)
{
    __shared__ float tile[32][33];
    const int nb = blockIdx.x * 32;
    const int kb = blockIdx.y * 32;
    const int tx = threadIdx.x;
    const int ty = threadIdx.y;
#pragma unroll
    for (int r = 0; r < 32; r += 8)
        tile[ty + r][tx] = W[(size_t)(kb + ty + r) * Ntot + nb + tx];
    __syncthreads();
#pragma unroll
    for (int r = 0; r < 32; r += 8) {
        float x = tile[tx][ty + r];               // W[kb+tx][nb+ty+r]
        __nv_bfloat16 h = __float2bfloat16_rn(x);
        __nv_bfloat16 l = __float2bfloat16_rn(x - __bfloat162float(h));
        size_t o = (size_t)(nb + ty + r) * DIM + kb + tx;
        hiT[o] = h;
        loT[o] = l;
    }
}

// ---------------------------------------------------------------------------
// Tensor-core GEMM via mma.sync (bf16x3): C[8192,Ntot] = A@B^T + bias
// A[M,1024] row-major (hi/lo), B[Ntot,1024] row-major = W^T (hi/lo).
// CTA: 128x128 tile, BK=32, 256 threads = 8 warps (2x4), warp tile 64x32.
// Smem tiles: [128 rows][40 bf16] (80B row stride -> conflict-free ldmatrix).
// 2-stage cp.async pipeline.
// ---------------------------------------------------------------------------
#define TPAD     40                    // padded row length in bf16 (80 bytes)
#define TILE_B   (128 * TPAD * 2)      // 10240 bytes per tile
#define STAGE_B  (4 * TILE_B)          // Ahi,Alo,Bhi,Blo = 40960 bytes
#define NCHUNKS  (DIM / 32)            // 32

__global__ __launch_bounds__(256, 1)
void gemm_mma(const __nv_bfloat16* __restrict__ Ahi, const __nv_bfloat16* __restrict__ Alo,
              const __nv_bfloat16* __restrict__ Bhi, const __nv_bfloat16* __restrict__ Blo,
              const float* __restrict__ bias, float* __restrict__ C, int Ntot)
{
    extern __shared__ __align__(128) char smem[];
    const uint32_t sb = smem_u32(smem);
    const int t    = threadIdx.x;
    const int wid  = t >> 5;
    const int lane = t & 31;
    const int bm   = blockIdx.y * 128;
    const int bn   = blockIdx.x * 128;
    const int wm   = (wid >> 2) * 64;   // warp row offset in tile
    const int wn   = (wid & 3) * 32;    // warp col offset in tile

    const __nv_bfloat16* srcs[4] = {Ahi, Alo, Bhi, Blo};

    // async-load one 4-tile K-chunk into stage s
    auto load_chunk = [&](int kc, int s) {
        const uint32_t stage = sb + s * STAGE_B;
#pragma unroll
        for (int r = 0; r < 4; r++) {
            const __nv_bfloat16* src = srcs[r];
            const int rowbase = (r < 2) ? bm : bn;
#pragma unroll
            for (int i = 0; i < 2; i++) {
                const int idx = t + i * 256;      // 0..511
                const int row = idx >> 2;         // 0..127
                const int c8  = idx & 3;          // 0..3 (x8 bf16)
                cp_async16(stage + r * TILE_B + row * 80 + c8 * 16,
                           src + (size_t)(rowbase + row) * DIM + kc * 32 + c8 * 8);
            }
        }
    };

    float acc[4][4][4];
#pragma unroll
    for (int i = 0; i < 4; i++)
#pragma unroll
        for (int j = 0; j < 4; j++)
#pragma unroll
            for (int q = 0; q < 4; q++) acc[i][j][q] = 0.f;

    load_chunk(0, 0);
    CP_COMMIT();

    for (int c = 0; c < NCHUNKS; ++c) {
        const int s = c & 1;
        if (c + 1 < NCHUNKS) {
            load_chunk(c + 1, s ^ 1);
            CP_COMMIT();
            CP_WAIT(1);                 // chunk c resident
        } else {
            CP_WAIT(0);
        }
        __syncthreads();

        const uint32_t stage = sb + s * STAGE_B;
        const uint32_t tAh = stage;
        const uint32_t tAl = stage + TILE_B;
        const uint32_t tBh = stage + 2 * TILE_B;
        const uint32_t tBl = stage + 3 * TILE_B;

#pragma unroll
        for (int kk = 0; kk < 2; kk++) {
            const uint32_t kbyte = (kk * 16 + (lane >> 4) * 8) * 2;
            // B fragments: 4 n8-groups, hi and lo
            uint32_t bh0[4], bh1[4], bl0[4], bl1[4];
#pragma unroll
            for (int p = 0; p < 2; p++) {
                const uint32_t boff = (uint32_t)(wn + p * 16 + (lane & 15)) * 80 + kbyte;
                ldmatrix_x4(bh0[2 * p], bh0[2 * p + 1], bh1[2 * p], bh1[2 * p + 1], tBh + boff);
                ldmatrix_x4(bl0[2 * p], bl0[2 * p + 1], bl1[2 * p], bl1[2 * p + 1], tBl + boff);
            }
#pragma unroll
            for (int im = 0; im < 4; im++) {
                const uint32_t aoff = (uint32_t)(wm + im * 16 + (lane & 15)) * 80 + kbyte;
                uint32_t ah[4], al[4];
                ldmatrix_x4(ah[0], ah[1], ah[2], ah[3], tAh + aoff);
                ldmatrix_x4(al[0], al[1], al[2], al[3], tAl + aoff);
#pragma unroll
                for (int jg = 0; jg < 4; jg++) {
                    mma16816(acc[im][jg], ah, bh0[jg], bh1[jg]);
                    mma16816(acc[im][jg], ah, bl0[jg], bl1[jg]);
                    mma16816(acc[im][jg], al, bh0[jg], bh1[jg]);
                }
            }
        }
        __syncthreads();
    }

    // epilogue: bias + fp32 store (each lane owns 2x2 floats per mma tile)
#pragma unroll
    for (int im = 0; im < 4; im++) {
        const int r0 = bm + wm + im * 16 + (lane >> 2);
        const int r1 = r0 + 8;
#pragma unroll
        for (int jg = 0; jg < 4; jg++) {
            const int col = bn + wn + jg * 8 + (lane & 3) * 2;
            const float2 bb = *(const float2*)(bias + col);
            float2 o0, o1;
            o0.x = acc[im][jg][0] + bb.x;
            o0.y = acc[im][jg][1] + bb.y;
            o1.x = acc[im][jg][2] + bb.x;
            o1.y = acc[im][jg][3] + bb.y;
            *(float2*)(C + (size_t)r0 * Ntot + col) = o0;
            *(float2*)(C + (size_t)r1 * Ntot + col) = o1;
        }
    }
}

// ---------------------------------------------------------------------------
// Flash attention (fp32, causal) — unchanged from the passing baseline.
// ---------------------------------------------------------------------------
#define SW(d, c) ((c) ^ (((((unsigned)(d)) >> 2) & 15u) << 2))

__global__ __launch_bounds__(256, 3)
void flash_attn()
{
    __shared__ __align__(16) float Qs[64][64];
    __shared__ __align__(16) float KP[64][64];
    __shared__ __align__(16) float Vs[64][64];

    const int qt = blockIdx.x;
    const int bh = blockIdx.y;
    const int b  = bh >> 4;
    const int h  = bh & 15;
    const int t  = threadIdx.x;
    const int ty = t >> 4;
    const int tx = t & 15;

    const float* qbase = g_qkv + (size_t)b * SEQ * 3072 + h * 64;
    const float* kbase = qbase + 1024;
    const float* vbase = qbase + 2048;

#pragma unroll
    for (int i = 0; i < 4; i++) {
        const int idx = t + i * 256;
        const int r   = idx >> 4;
        const int d4  = (idx & 15) << 2;
        float4 q = *(const float4*)(qbase + (size_t)(qt * 64 + r) * 3072 + d4);
        Qs[d4 + 0][SW(d4 + 0, r)] = q.x * 0.125f;
        Qs[d4 + 1][SW(d4 + 1, r)] = q.y * 0.125f;
        Qs[d4 + 2][SW(d4 + 2, r)] = q.z * 0.125f;
        Qs[d4 + 3][SW(d4 + 3, r)] = q.w * 0.125f;
    }

    float o[4][4];
    float m[4], l[4];
#pragma unroll
    for (int i = 0; i < 4; i++) {
        m[i] = -CUDART_INF_F;
        l[i] = 0.f;
#pragma unroll
        for (int j = 0; j < 4; j++) o[i][j] = 0.f;
    }

    for (int j = 0; j <= qt; j++) {
        __syncthreads();
#pragma unroll
        for (int i = 0; i < 4; i++) {
            const int idx = t + i * 256;
            const int r   = idx >> 4;
            const int d4  = (idx & 15) << 2;
            float4 k = *(const float4*)(kbase + (size_t)(j * 64 + r) * 3072 + d4);
            KP[d4 + 0][SW(d4 + 0, r)] = k.x;
            KP[d4 + 1][SW(d4 + 1, r)] = k.y;
            KP[d4 + 2][SW(d4 + 2, r)] = k.z;
            KP[d4 + 3][SW(d4 + 3, r)] = k.w;
            *(float4*)&Vs[r][d4] =
                *(const float4*)(vbase + (size_t)(j * 64 + r) * 3072 + d4);
        }
        __syncthreads();

        float s[4][4];
#pragma unroll
        for (int i = 0; i < 4; i++)
#pragma unroll
            for (int jj = 0; jj < 4; jj++) s[i][jj] = 0.f;

#pragma unroll
        for (int d = 0; d < 64; d++) {
            float4 q4 = *(float4*)&Qs[d][SW(d, ty * 4)];
            float4 k4 = *(float4*)&KP[d][SW(d, tx * 4)];
            const float qv[4] = {q4.x, q4.y, q4.z, q4.w};
            const float kv[4] = {k4.x, k4.y, k4.z, k4.w};
#pragma unroll
            for (int i = 0; i < 4; i++)
#pragma unroll
                for (int jj = 0; jj < 4; jj++)
                    s[i][jj] = fmaf(qv[i], kv[jj], s[i][jj]);
        }

        if (j == qt) {
#pragma unroll
            for (int i = 0; i < 4; i++)
#pragma unroll
                for (int jj = 0; jj < 4; jj++)
                    if (tx * 4 + jj > ty * 4 + i) s[i][jj] = -CUDART_INF_F;
        }

        __syncthreads();

#pragma unroll
        for (int i = 0; i < 4; i++) {
            float mx = fmaxf(fmaxf(s[i][0], s[i][1]), fmaxf(s[i][2], s[i][3]));
#pragma unroll
            for (int off = 1; off < 16; off <<= 1)
                mx = fmaxf(mx, __shfl_xor_sync(0xffffffffu, mx, off));
            const float mn   = fmaxf(m[i], mx);
            const float corr = __expf(m[i] - mn);
            float ps = 0.f;
#pragma unroll
            for (int jj = 0; jj < 4; jj++) {
                const float p = __expf(s[i][jj] - mn);
                s[i][jj] = p;
                ps += p;
            }
#pragma unroll
            for (int off = 1; off < 16; off <<= 1)
                ps += __shfl_xor_sync(0xffffffffu, ps, off);
            l[i] = l[i] * corr + ps;
            m[i] = mn;
#pragma unroll
            for (int jj = 0; jj < 4; jj++) o[i][jj] *= corr;
            *(float4*)&KP[ty * 4 + i][tx * 4] =
                make_float4(s[i][0], s[i][1], s[i][2], s[i][3]);
        }
        __syncthreads();

#pragma unroll
        for (int k = 0; k < 64; k++) {
            float4 v4 = *(float4*)&Vs[k][tx * 4];
            const float vv[4] = {v4.x, v4.y, v4.z, v4.w};
            const float p0 = KP[ty * 4 + 0][k];
            const float p1 = KP[ty * 4 + 1][k];
            const float p2 = KP[ty * 4 + 2][k];
            const float p3 = KP[ty * 4 + 3][k];
#pragma unroll
            for (int jj = 0; jj < 4; jj++) {
                o[0][jj] = fmaf(p0, vv[jj], o[0][jj]);
                o[1][jj] = fmaf(p1, vv[jj], o[1][jj]);
                o[2][jj] = fmaf(p2, vv[jj], o[2][jj]);
                o[3][jj] = fmaf(p3, vv[jj], o[3][jj]);
            }
        }
    }

#pragma unroll
    for (int i = 0; i < 4; i++) {
        const float inv = 1.f / l[i];
        const size_t row = (size_t)b * SEQ + qt * 64 + ty * 4 + i;
        *(float4*)&g_att[row * DIM + h * 64 + tx * 4] =
            make_float4(o[i][0] * inv, o[i][1] * inv, o[i][2] * inv, o[i][3] * inv);
    }
}

// ---------------------------------------------------------------------------
extern "C" void kernel_launch(void* const* d_in, const int* in_sizes, int n_in,
                              void* d_out, int out_size)
{
    const float* x      = (const float*)d_in[0];
    const float* w_qkv  = (const float*)d_in[1];
    const float* b_qkv  = (const float*)d_in[2];
    const float* w_proj = (const float*)d_in[3];
    const float* b_proj = (const float*)d_in[4];
    float* out = (float*)d_out;

    float *qkv_p, *att_p;
    __nv_bfloat16 *xhi, *xlo, *ahi, *alo, *wqh, *wql, *wph, *wpl;
    cudaGetSymbolAddress((void**)&qkv_p, g_qkv);
    cudaGetSymbolAddress((void**)&att_p, g_att);
    cudaGetSymbolAddress((void**)&xhi, g_xhi);
    cudaGetSymbolAddress((void**)&xlo, g_xlo);
    cudaGetSymbolAddress((void**)&ahi, g_ahi);
    cudaGetSymbolAddress((void**)&alo, g_alo);
    cudaGetSymbolAddress((void**)&wqh, g_wqhiT);
    cudaGetSymbolAddress((void**)&wql, g_wqloT);
    cudaGetSymbolAddress((void**)&wph, g_wphiT);
    cudaGetSymbolAddress((void**)&wpl, g_wploT);

    const int smem_bytes = 2 * STAGE_B;   // 81920
    cudaFuncSetAttribute(gemm_mma, cudaFuncAttributeMaxDynamicSharedMemorySize,
                         smem_bytes);

    // 1) split x -> bf16 hi/lo
    {
        int n4 = MTOT * DIM / 4;
        cvt_split<<<(n4 + 255) / 256, 256>>>(x, xhi, xlo, n4);
    }
    // 2) transpose+split weights
    transpose_split<<<dim3(3 * DIM / 32, DIM / 32), dim3(32, 8)>>>(w_qkv, wqh, wql, 3 * DIM);
    transpose_split<<<dim3(DIM / 32, DIM / 32), dim3(32, 8)>>>(w_proj, wph, wpl, DIM);
    // 3) QKV projection on tensor cores (mma.sync bf16x3)
    gemm_mma<<<dim3(3 * DIM / 128, MTOT / 128), 256, smem_bytes>>>(
        xhi, xlo, wqh, wql, b_qkv, qkv_p, 3 * DIM);
    // 4) causal flash attention (fp32)
    flash_attn<<<dim3(SEQ / 64, BATCH * HEADS), 256>>>();
    // 5) split attention output
    {
        int n4 = MTOT * DIM / 4;
        cvt_split<<<(n4 + 255) / 256, 256>>>(att_p, ahi, alo, n4);
    }
    // 6) output projection on tensor cores
    gemm_mma<<<dim3(DIM / 128, MTOT / 128), 256, smem_bytes>>>(
        ahi, alo, wph, wpl, b_proj, out, DIM);
}

// round 14
// speedup vs baseline: 1.0037x; 1.0037x over previous
#include <cuda_runtime.h>
#include <cuda_bf16.h>
#include <math_constants.h>
#include <cstdint>

// Problem constants
#define BATCH 8
#define SEQ   1024
#define DIM   1024
#define HEADS 16
#define HDIM  64
#define MTOT  (BATCH * SEQ)   // 8192

// ---------------------------------------------------------------------------
// Scratch (device globals — allocation-free rule)
// ---------------------------------------------------------------------------
__device__ __align__(16) float g_qkv[MTOT * 3 * DIM];   // [8192, 3072]
__device__ __align__(16) float g_att[MTOT * DIM];       // [8192, 1024]
__device__ __align__(16) __nv_bfloat16 g_xhi[MTOT * DIM];
__device__ __align__(16) __nv_bfloat16 g_xlo[MTOT * DIM];
__device__ __align__(16) __nv_bfloat16 g_ahi[MTOT * DIM];
__device__ __align__(16) __nv_bfloat16 g_alo[MTOT * DIM];
__device__ __align__(16) __nv_bfloat16 g_wqhiT[3 * DIM * DIM];  // [3072, 1024]
__device__ __align__(16) __nv_bfloat16 g_wqloT[3 * DIM * DIM];
__device__ __align__(16) __nv_bfloat16 g_wphiT[DIM * DIM];      // [1024, 1024]
__device__ __align__(16) __nv_bfloat16 g_wploT[DIM * DIM];

// ---------------------------------------------------------------------------
// Portable PTX helpers (NO 'a'-suffix features — harness compiles compute_103)
// ---------------------------------------------------------------------------
__device__ __forceinline__ uint32_t smem_u32(const void* p) {
    uint32_t a;
    asm("{ .reg .u64 t; cvta.to.shared.u64 t, %1; cvt.u32.u64 %0, t; }"
        : "=r"(a) : "l"(p));
    return a;
}

__device__ __forceinline__ void cp_async16(uint32_t saddr, const void* gaddr) {
    asm volatile("cp.async.cg.shared.global [%0], [%1], 16;"
                 :: "r"(saddr), "l"(gaddr));
}
#define CP_COMMIT()  asm volatile("cp.async.commit_group;" ::: "memory")
#define CP_WAIT(n)   asm volatile("cp.async.wait_group %0;" :: "n"(n) : "memory")

__device__ __forceinline__ void ldmatrix_x4(uint32_t& r0, uint32_t& r1,
                                            uint32_t& r2, uint32_t& r3,
                                            uint32_t addr) {
    asm volatile("ldmatrix.sync.aligned.m8n8.x4.shared.b16 {%0,%1,%2,%3}, [%4];"
                 : "=r"(r0), "=r"(r1), "=r"(r2), "=r"(r3) : "r"(addr));
}

__device__ __forceinline__ void mma16816(float* d, const uint32_t* a,
                                         uint32_t b0, uint32_t b1) {
    asm volatile(
        "mma.sync.aligned.m16n8k16.row.col.f32.bf16.bf16.f32 "
        "{%0,%1,%2,%3}, {%4,%5,%6,%7}, {%8,%9}, {%0,%1,%2,%3};"
        : "+f"(d[0]), "+f"(d[1]), "+f"(d[2]), "+f"(d[3])
        : "r"(a[0]), "r"(a[1]), "r"(a[2]), "r"(a[3]), "r"(b0), "r"(b1));
}

// ---------------------------------------------------------------------------
// fp32 -> bf16 hi/lo split (vectorized x4)
// ---------------------------------------------------------------------------
__global__ void cvt_split(const float* __restrict__ src,
                          __nv_bfloat16* __restrict__ hi,
                          __nv_bfloat16* __restrict__ lo, int n4)
{
    int i = blockIdx.x * blockDim.x + threadIdx.x;
    if (i >= n4) return;
    float4 v = ((const float4*)src)[i];
    __nv_bfloat16 h0 = __float2bfloat16_rn(v.x);
    __nv_bfloat16 h1 = __float2bfloat16_rn(v.y);
    __nv_bfloat16 h2 = __float2bfloat16_rn(v.z);
    __nv_bfloat16 h3 = __float2bfloat16_rn(v.w);
    __nv_bfloat16 l0 = __float2bfloat16_rn(v.x - __bfloat162float(h0));
    __nv_bfloat16 l1 = __float2bfloat16_rn(v.y - __bfloat162float(h1));
    __nv_bfloat16 l2 = __float2bfloat16_rn(v.z - __bfloat162float(h2));
    __nv_bfloat16 l3 = __float2bfloat16_rn(v.w - __bfloat162float(h3));
    __nv_bfloat162* hp = (__nv_bfloat162*)hi;
    __nv_bfloat162* lp = (__nv_bfloat162*)lo;
    hp[i * 2 + 0] = __nv_bfloat162(h0, h1);
    hp[i * 2 + 1] = __nv_bfloat162(h2, h3);
    lp[i * 2 + 0] = __nv_bfloat162(l0, l1);
    lp[i * 2 + 1] = __nv_bfloat162(l2, l3);
}

// ---------------------------------------------------------------------------
// Transpose W[K=1024, Ntot] -> hiT/loT [Ntot, 1024] (bf16 split)
// ---------------------------------------------------------------------------
__global__ void transpose_split(const float* __restrict__ W,
                                __nv_bfloat16* __restrict__ hiT,
                                __nv_bfloat16* __restrict__ loT, int Ntot)
{
    __shared__ float tile[32][33];
    const int nb = blockIdx.x * 32;
    const int kb = blockIdx.y * 32;
    const int tx = threadIdx.x;
    const int ty = threadIdx.y;
#pragma unroll
    for (int r = 0; r < 32; r += 8)
        tile[ty + r][tx] = W[(size_t)(kb + ty + r) * Ntot + nb + tx];
    __syncthreads();
#pragma unroll
    for (int r = 0; r < 32; r += 8) {
        float x = tile[tx][ty + r];               // W[kb+tx][nb+ty+r]
        __nv_bfloat16 h = __float2bfloat16_rn(x);
        __nv_bfloat16 l = __float2bfloat16_rn(x - __bfloat162float(h));
        size_t o = (size_t)(nb + ty + r) * DIM + kb + tx;
        hiT[o] = h;
        loT[o] = l;
    }
}

// ---------------------------------------------------------------------------
// Tensor-core GEMM via mma.sync (bf16x3): C[8192,Ntot] = A@B^T + bias
// A[M,1024] row-major (hi/lo), B[Ntot,1024] row-major = W^T (hi/lo).
// CTA: 128x128 tile, BK=32, 256 threads = 8 warps (2x4), warp tile 64x32.
// Smem tiles: [128 rows][40 bf16] (80B row stride -> conflict-free ldmatrix).
// 2-stage cp.async pipeline.
// ---------------------------------------------------------------------------
#define TPAD     40                    // padded row length in bf16 (80 bytes)
#define TILE_B   (128 * TPAD * 2)      // 10240 bytes per tile
#define STAGE_B  (4 * TILE_B)          // Ahi,Alo,Bhi,Blo = 40960 bytes
#define NCHUNKS  (DIM / 32)            // 32

__global__ __launch_bounds__(256, 1)
void gemm_mma(const __nv_bfloat16* __restrict__ Ahi, const __nv_bfloat16* __restrict__ Alo,
              const __nv_bfloat16* __restrict__ Bhi, const __nv_bfloat16* __restrict__ Blo,
              const float* __restrict__ bias, float* __restrict__ C, int Ntot)
{
    extern __shared__ __align__(128) char smem[];
    const uint32_t sb = smem_u32(smem);
    const int t    = threadIdx.x;
    const int wid  = t >> 5;
    const int lane = t & 31;
    const int bm   = blockIdx.y * 128;
    const int bn   = blockIdx.x * 128;
    const int wm   = (wid >> 2) * 64;   // warp row offset in tile
    const int wn   = (wid & 3) * 32;    // warp col offset in tile

    const __nv_bfloat16* srcs[4] = {Ahi, Alo, Bhi, Blo};

    // async-load one 4-tile K-chunk into stage s
    auto load_chunk = [&](int kc, int s) {
        const uint32_t stage = sb + s * STAGE_B;
#pragma unroll
        for (int r = 0; r < 4; r++) {
            const __nv_bfloat16* src = srcs[r];
            const int rowbase = (r < 2) ? bm : bn;
#pragma unroll
            for (int i = 0; i < 2; i++) {
                const int idx = t + i * 256;      // 0..511
                const int row = idx >> 2;         // 0..127
                const int c8  = idx & 3;          // 0..3 (x8 bf16)
                cp_async16(stage + r * TILE_B + row * 80 + c8 * 16,
                           src + (size_t)(rowbase + row) * DIM + kc * 32 + c8 * 8);
            }
        }
    };

    float acc[4][4][4];
#pragma unroll
    for (int i = 0; i < 4; i++)
#pragma unroll
        for (int j = 0; j < 4; j++)
#pragma unroll
            for (int q = 0; q < 4; q++) acc[i][j][q] = 0.f;

    load_chunk(0, 0);
    CP_COMMIT();

    for (int c = 0; c < NCHUNKS; ++c) {
        const int s = c & 1;
        if (c + 1 < NCHUNKS) {
            load_chunk(c + 1, s ^ 1);
            CP_COMMIT();
            CP_WAIT(1);                 // chunk c resident
        } else {
            CP_WAIT(0);
        }
        __syncthreads();

        const uint32_t stage = sb + s * STAGE_B;
        const uint32_t tAh = stage;
        const uint32_t tAl = stage + TILE_B;
        const uint32_t tBh = stage + 2 * TILE_B;
        const uint32_t tBl = stage + 3 * TILE_B;

#pragma unroll
        for (int kk = 0; kk < 2; kk++) {
            const uint32_t kbyte = (kk * 16 + (lane >> 4) * 8) * 2;
            // B fragments: 4 n8-groups, hi and lo
            uint32_t bh0[4], bh1[4], bl0[4], bl1[4];
#pragma unroll
            for (int p = 0; p < 2; p++) {
                const uint32_t boff = (uint32_t)(wn + p * 16 + (lane & 15)) * 80 + kbyte;
                ldmatrix_x4(bh0[2 * p], bh0[2 * p + 1], bh1[2 * p], bh1[2 * p + 1], tBh + boff);
                ldmatrix_x4(bl0[2 * p], bl0[2 * p + 1], bl1[2 * p], bl1[2 * p + 1], tBl + boff);
            }
#pragma unroll
            for (int im = 0; im < 4; im++) {
                const uint32_t aoff = (uint32_t)(wm + im * 16 + (lane & 15)) * 80 + kbyte;
                uint32_t ah[4], al[4];
                ldmatrix_x4(ah[0], ah[1], ah[2], ah[3], tAh + aoff);
                ldmatrix_x4(al[0], al[1], al[2], al[3], tAl + aoff);
#pragma unroll
                for (int jg = 0; jg < 4; jg++) {
                    mma16816(acc[im][jg], ah, bh0[jg], bh1[jg]);
                    mma16816(acc[im][jg], ah, bl0[jg], bl1[jg]);
                    mma16816(acc[im][jg], al, bh0[jg], bh1[jg]);
                }
            }
        }
        __syncthreads();
    }

    // epilogue: bias + fp32 store (each lane owns 2x2 floats per mma tile)
#pragma unroll
    for (int im = 0; im < 4; im++) {
        const int r0 = bm + wm + im * 16 + (lane >> 2);
        const int r1 = r0 + 8;
#pragma unroll
        for (int jg = 0; jg < 4; jg++) {
            const int col = bn + wn + jg * 8 + (lane & 3) * 2;
            const float2 bb = *(const float2*)(bias + col);
            float2 o0, o1;
            o0.x = acc[im][jg][0] + bb.x;
            o0.y = acc[im][jg][1] + bb.y;
            o1.x = acc[im][jg][2] + bb.x;
            o1.y = acc[im][jg][3] + bb.y;
            *(float2*)(C + (size_t)r0 * Ntot + col) = o0;
            *(float2*)(C + (size_t)r1 * Ntot + col) = o1;
        }
    }
}

// ---------------------------------------------------------------------------
// Flash attention (fp32, causal) — unchanged from the passing baseline.
// ---------------------------------------------------------------------------
#define SW(d, c) ((c) ^ (((((unsigned)(d)) >> 2) & 15u) << 2))

__global__ __launch_bounds__(256, 3)
void flash_attn()
{
    __shared__ __align__(16) float Qs[64][64];
    __shared__ __align__(16) float KP[64][64];
    __shared__ __align__(16) float Vs[64][64];

    const int qt = blockIdx.x;
    const int bh = blockIdx.y;
    const int b  = bh >> 4;
    const int h  = bh & 15;
    const int t  = threadIdx.x;
    const int ty = t >> 4;
    const int tx = t & 15;

    const float* qbase = g_qkv + (size_t)b * SEQ * 3072 + h * 64;
    const float* kbase = qbase + 1024;
    const float* vbase = qbase + 2048;

#pragma unroll
    for (int i = 0; i < 4; i++) {
        const int idx = t + i * 256;
        const int r   = idx >> 4;
        const int d4  = (idx & 15) << 2;
        float4 q = *(const float4*)(qbase + (size_t)(qt * 64 + r) * 3072 + d4);
        Qs[d4 + 0][SW(d4 + 0, r)] = q.x * 0.125f;
        Qs[d4 + 1][SW(d4 + 1, r)] = q.y * 0.125f;
        Qs[d4 + 2][SW(d4 + 2, r)] = q.z * 0.125f;
        Qs[d4 + 3][SW(d4 + 3, r)] = q.w * 0.125f;
    }

    float o[4][4];
    float m[4], l[4];
#pragma unroll
    for (int i = 0; i < 4; i++) {
        m[i] = -CUDART_INF_F;
        l[i] = 0.f;
#pragma unroll
        for (int j = 0; j < 4; j++) o[i][j] = 0.f;
    }

    for (int j = 0; j <= qt; j++) {
        __syncthreads();
#pragma unroll
        for (int i = 0; i < 4; i++) {
            const int idx = t + i * 256;
            const int r   = idx >> 4;
            const int d4  = (idx & 15) << 2;
            float4 k = *(const float4*)(kbase + (size_t)(j * 64 + r) * 3072 + d4);
            KP[d4 + 0][SW(d4 + 0, r)] = k.x;
            KP[d4 + 1][SW(d4 + 1, r)] = k.y;
            KP[d4 + 2][SW(d4 + 2, r)] = k.z;
            KP[d4 + 3][SW(d4 + 3, r)] = k.w;
            *(float4*)&Vs[r][d4] =
                *(const float4*)(vbase + (size_t)(j * 64 + r) * 3072 + d4);
        }
        __syncthreads();

        float s[4][4];
#pragma unroll
        for (int i = 0; i < 4; i++)
#pragma unroll
            for (int jj = 0; jj < 4; jj++) s[i][jj] = 0.f;

#pragma unroll
        for (int d = 0; d < 64; d++) {
            float4 q4 = *(float4*)&Qs[d][SW(d, ty * 4)];
            float4 k4 = *(float4*)&KP[d][SW(d, tx * 4)];
            const float qv[4] = {q4.x, q4.y, q4.z, q4.w};
            const float kv[4] = {k4.x, k4.y, k4.z, k4.w};
#pragma unroll
            for (int i = 0; i < 4; i++)
#pragma unroll
                for (int jj = 0; jj < 4; jj++)
                    s[i][jj] = fmaf(qv[i], kv[jj], s[i][jj]);
        }

        if (j == qt) {
#pragma unroll
            for (int i = 0; i < 4; i++)
#pragma unroll
                for (int jj = 0; jj < 4; jj++)
                    if (tx * 4 + jj > ty * 4 + i) s[i][jj] = -CUDART_INF_F;
        }

        __syncthreads();

#pragma unroll
        for (int i = 0; i < 4; i++) {
            float mx = fmaxf(fmaxf(s[i][0], s[i][1]), fmaxf(s[i][2], s[i][3]));
#pragma unroll
            for (int off = 1; off < 16; off <<= 1)
                mx = fmaxf(mx, __shfl_xor_sync(0xffffffffu, mx, off));
            const float mn   = fmaxf(m[i], mx);
            const float corr = __expf(m[i] - mn);
            float ps = 0.f;
#pragma unroll
            for (int jj = 0; jj < 4; jj++) {
                const float p = __expf(s[i][jj] - mn);
                s[i][jj] = p;
                ps += p;
            }
#pragma unroll
            for (int off = 1; off < 16; off <<= 1)
                ps += __shfl_xor_sync(0xffffffffu, ps, off);
            l[i] = l[i] * corr + ps;
            m[i] = mn;
#pragma unroll
            for (int jj = 0; jj < 4; jj++) o[i][jj] *= corr;
            *(float4*)&KP[ty * 4 + i][tx * 4] =
                make_float4(s[i][0], s[i][1], s[i][2], s[i][3]);
        }
        __syncthreads();

#pragma unroll
        for (int k = 0; k < 64; k++) {
            float4 v4 = *(float4*)&Vs[k][tx * 4];
            const float vv[4] = {v4.x, v4.y, v4.z, v4.w};
            const float p0 = KP[ty * 4 + 0][k];
            const float p1 = KP[ty * 4 + 1][k];
            const float p2 = KP[ty * 4 + 2][k];
            const float p3 = KP[ty * 4 + 3][k];
#pragma unroll
            for (int jj = 0; jj < 4; jj++) {
                o[0][jj] = fmaf(p0, vv[jj], o[0][jj]);
                o[1][jj] = fmaf(p1, vv[jj], o[1][jj]);
                o[2][jj] = fmaf(p2, vv[jj], o[2][jj]);
                o[3][jj] = fmaf(p3, vv[jj], o[3][jj]);
            }
        }
    }

#pragma unroll
    for (int i = 0; i < 4; i++) {
        const float inv = 1.f / l[i];
        const size_t row = (size_t)b * SEQ + qt * 64 + ty * 4 + i;
        *(float4*)&g_att[row * DIM + h * 64 + tx * 4] =
            make_float4(o[i][0] * inv, o[i][1] * inv, o[i][2] * inv, o[i][3] * inv);
    }
}

// ---------------------------------------------------------------------------
extern "C" void kernel_launch(void* const* d_in, const int* in_sizes, int n_in,
                              void* d_out, int out_size)
{
    const float* x      = (const float*)d_in[0];
    const float* w_qkv  = (const float*)d_in[1];
    const float* b_qkv  = (const float*)d_in[2];
    const float* w_proj = (const float*)d_in[3];
    const float* b_proj = (const float*)d_in[4];
    float* out = (float*)d_out;

    float *qkv_p, *att_p;
    __nv_bfloat16 *xhi, *xlo, *ahi, *alo, *wqh, *wql, *wph, *wpl;
    cudaGetSymbolAddress((void**)&qkv_p, g_qkv);
    cudaGetSymbolAddress((void**)&att_p, g_att);
    cudaGetSymbolAddress((void**)&xhi, g_xhi);
    cudaGetSymbolAddress((void**)&xlo, g_xlo);
    cudaGetSymbolAddress((void**)&ahi, g_ahi);
    cudaGetSymbolAddress((void**)&alo, g_alo);
    cudaGetSymbolAddress((void**)&wqh, g_wqhiT);
    cudaGetSymbolAddress((void**)&wql, g_wqloT);
    cudaGetSymbolAddress((void**)&wph, g_wphiT);
    cudaGetSymbolAddress((void**)&wpl, g_wploT);

    const int smem_bytes = 2 * STAGE_B;   // 81920
    cudaFuncSetAttribute(gemm_mma, cudaFuncAttributeMaxDynamicSharedMemorySize,
                         smem_bytes);

    // 1) split x -> bf16 hi/lo
    {
        int n4 = MTOT * DIM / 4;
        cvt_split<<<(n4 + 255) / 256, 256>>>(x, xhi, xlo, n4);
    }
    // 2) transpose+split weights
    transpose_split<<<dim3(3 * DIM / 32, DIM / 32), dim3(32, 8)>>>(w_qkv, wqh, wql, 3 * DIM);
    transpose_split<<<dim3(DIM / 32, DIM / 32), dim3(32, 8)>>>(w_proj, wph, wpl, DIM);
    // 3) QKV projection on tensor cores (mma.sync bf16x3)
    gemm_mma<<<dim3(3 * DIM / 128, MTOT / 128), 256, smem_bytes>>>(
        xhi, xlo, wqh, wql, b_qkv, qkv_p, 3 * DIM);
    // 4) causal flash attention (fp32)
    flash_attn<<<dim3(SEQ / 64, BATCH * HEADS), 256>>>();
    // 5) split attention output
    {
        int n4 = MTOT * DIM / 4;
        cvt_split<<<(n4 + 255) / 256, 256>>>(att_p, ahi, alo, n4);
    }
    // 6) output projection on tensor cores
    gemm_mma<<<dim3(DIM / 128, MTOT / 128), 256, smem_bytes>>>(
        ahi, alo, wph, wpl, b_proj, out, DIM);
}